// round 11
// baseline (speedup 1.0000x reference)
#include <cuda_runtime.h>
#include <cstdint>

// Batched GEMM, mma.sync fp16 m16n8k16 + ldmatrix.
// Round-11: register-free staging. cp.async stages raw fp32 (2 buffers);
// a per-thread convert pass (LDS.128 -> cvt.rn.f16x2 -> STS.64) produces the
// fp16 ldmatrix tiles (2 buffers). The 64 LDG-prefetch registers of round 9
// are freed and spent on prefetching BOTH k16 fragment sets up-front.
//
//   x:    [B=16, M=256, K=512]  (K contiguous)
//   path: [B=16, K=512, N=2048] (N contiguous)
//   out:  [B=16, M=256, N=2048]
//
// CTA 128x128, BK=32, 128 threads (4 warps, 64x64 warp tiles), 2 CTAs/SM.

constexpr int Mm = 256, Kk = 512, Nn = 2048;
constexpr int BM = 128, BN = 128, BK = 32;
constexpr int THREADS = 128;
constexpr int KT = Kk / BK;  // 16

// fp32 staging: A 128x32 (16KB) + B 32x128 (16KB), linear chunk layout
constexpr int S32_B = 32768;           // one fp32 stage
constexpr int B32_OFF = 16384;         // B within fp32 stage
// fp16 tiles (ldmatrix layout, round-9 proven strides)
constexpr int A_STRIDE_H = 40;         // 80B rows
constexpr int B_STRIDE_H = 136;        // 272B rows
constexpr int AH_B = BM * A_STRIDE_H * 2;   // 10240
constexpr int BH_B = BK * B_STRIDE_H * 2;   // 8704
constexpr int SH_B = AH_B + BH_B;           // 18944
constexpr int FP16_OFF = 2 * S32_B;         // 65536
constexpr int SMEM_BYTES = FP16_OFF + 2 * SH_B;  // 103424

__device__ __forceinline__ uint32_t smem_u32(const void* ptr) {
    uint32_t a;
    asm("{ .reg .u64 t; cvta.to.shared.u64 t, %1; cvt.u32.u64 %0, t; }"
        : "=r"(a) : "l"(ptr));
    return a;
}
__device__ __forceinline__ uint32_t h2pack(float lo, float hi) {
    uint32_t r;
    asm("cvt.rn.f16x2.f32 %0, %1, %2;" : "=r"(r) : "f"(hi), "f"(lo));
    return r;
}
__device__ __forceinline__ void cp_async16(uint32_t dst, const void* src) {
    asm volatile("cp.async.cg.shared.global [%0], [%1], 16;"
                 :: "r"(dst), "l"(src) : "memory");
}
__device__ __forceinline__ void cp_commit() {
    asm volatile("cp.async.commit_group;" ::: "memory");
}
template <int N>
__device__ __forceinline__ void cp_wait() {
    asm volatile("cp.async.wait_group %0;" :: "n"(N) : "memory");
}
__device__ __forceinline__ void ldmatrix_x4(uint32_t& r0, uint32_t& r1,
                                            uint32_t& r2, uint32_t& r3, uint32_t addr) {
    asm volatile("ldmatrix.sync.aligned.m8n8.x4.shared.b16 {%0,%1,%2,%3}, [%4];"
                 : "=r"(r0), "=r"(r1), "=r"(r2), "=r"(r3) : "r"(addr));
}
__device__ __forceinline__ void ldmatrix_x4_trans(uint32_t& r0, uint32_t& r1,
                                                  uint32_t& r2, uint32_t& r3, uint32_t addr) {
    asm volatile("ldmatrix.sync.aligned.m8n8.x4.trans.shared.b16 {%0,%1,%2,%3}, [%4];"
                 : "=r"(r0), "=r"(r1), "=r"(r2), "=r"(r3) : "r"(addr));
}
__device__ __forceinline__ void mma_f16(float& c0, float& c1, float& c2, float& c3,
                                        uint32_t a0, uint32_t a1, uint32_t a2, uint32_t a3,
                                        uint32_t b0, uint32_t b1) {
    asm volatile(
        "mma.sync.aligned.m16n8k16.row.col.f32.f16.f16.f32 "
        "{%0,%1,%2,%3}, {%4,%5,%6,%7}, {%8,%9}, {%0,%1,%2,%3};"
        : "+f"(c0), "+f"(c1), "+f"(c2), "+f"(c3)
        : "r"(a0), "r"(a1), "r"(a2), "r"(a3), "r"(b0), "r"(b1));
}

__global__ __launch_bounds__(THREADS, 2)
void bmm_mma_f16_cp(const float* __restrict__ A,
                    const float* __restrict__ B,
                    float* __restrict__ C) {
    extern __shared__ char smem[];
    const uint32_t sb = smem_u32(smem);

    const int tid = threadIdx.x;
    const int wid = tid >> 5;
    const int lane = tid & 31;
    const int b  = blockIdx.z;
    const int by = blockIdx.y;
    const int n0 = blockIdx.x * BN;

    const float* Ab = A + (size_t)b * Mm * Kk + (size_t)by * BM * Kk;
    const float* Bb = B + (size_t)b * Kk * Nn + n0;
    float*       Cb = C + (size_t)b * Mm * Nn + (size_t)by * BM * Nn + n0;

    // ---- cp.async: 8 A chunks + 8 B chunks per thread, linear layout ----
    // chunk c = tid + 128*j. A: row=c>>3, k4=(c&7)*4. B: row=c>>5, n4=(c&31)*4.
    auto issue_stage = [&](int kt, int s) {
        const uint32_t base = sb + s * S32_B;
        const float* Asrc = Ab + (size_t)kt * BK;
        const float* Bsrc = Bb + (size_t)kt * BK * Nn;
#pragma unroll
        for (int j = 0; j < 8; j++) {
            int c = tid + 128 * j;
            cp_async16(base + c * 16, Asrc + (size_t)(c >> 3) * Kk + (c & 7) * 4);
        }
#pragma unroll
        for (int j = 0; j < 8; j++) {
            int c = tid + 128 * j;
            cp_async16(base + B32_OFF + c * 16,
                       Bsrc + (size_t)(c >> 5) * Nn + (c & 31) * 4);
        }
        cp_commit();
    };

    // ---- convert pass: fp32 stage s -> fp16 tile s (thread-private chunks) ----
    auto convert_stage = [&](int s) {
        const char* b32 = smem + s * S32_B;
        char* bh = smem + FP16_OFF + s * SH_B;
#pragma unroll
        for (int j = 0; j < 8; j++) {
            int c = tid + 128 * j;
            float4 v = *(const float4*)(b32 + c * 16);
            uint2 p = make_uint2(h2pack(v.x, v.y), h2pack(v.z, v.w));
            *(uint2*)(bh + (c >> 3) * (A_STRIDE_H * 2) + (c & 7) * 8) = p;
        }
#pragma unroll
        for (int j = 0; j < 8; j++) {
            int c = tid + 128 * j;
            float4 v = *(const float4*)(b32 + B32_OFF + c * 16);
            uint2 p = make_uint2(h2pack(v.x, v.y), h2pack(v.z, v.w));
            *(uint2*)(bh + AH_B + (c >> 5) * (B_STRIDE_H * 2) + (c & 31) * 8) = p;
        }
    };

    // ---- compute mapping: 4 warps, 2x2 of 64x64 warp tiles ----
    const int warp_m = wid >> 1;
    const int warp_n = wid & 1;
    const int m_base = warp_m * 64;
    const int nb     = warp_n * 64;
    const int g = lane >> 2;
    const int t = lane & 3;
    const int lrow8 = (lane & 7) + ((lane >> 3) & 1) * 8;
    const int lk8   = ((lane >> 4) & 1) * 8;

    float acc[4][8][4];
#pragma unroll
    for (int i = 0; i < 4; i++)
#pragma unroll
        for (int j = 0; j < 8; j++)
#pragma unroll
            for (int r = 0; r < 4; r++) acc[i][j][r] = 0.0f;

    uint32_t af[2][4][4];   // [ks][m16 tile][reg]
    uint32_t bf[2][4][4];   // [ks][n16 tile][reg]

    // ---- prologue ----
    issue_stage(0, 0);
    issue_stage(1, 1);
    cp_wait<1>();           // stage 0 landed
    convert_stage(0);
    __syncthreads();

#pragma unroll 1
    for (int kt = 0; kt < KT; kt++) {
        const int p = kt & 1;
        const uint32_t AHb = sb + FP16_OFF + p * SH_B;
        const uint32_t BHb = AHb + AH_B;

        // fragment prefetch: both k16 steps up-front (16 ldmatrix)
#pragma unroll
        for (int ks = 0; ks < 2; ks++) {
            const int k0 = ks * 16;
#pragma unroll
            for (int i = 0; i < 4; i++) {
                uint32_t addr = AHb
                    + (m_base + i * 16 + lrow8) * (A_STRIDE_H * 2)
                    + (k0 + lk8) * 2;
                ldmatrix_x4(af[ks][i][0], af[ks][i][1], af[ks][i][2], af[ks][i][3], addr);
            }
#pragma unroll
            for (int j2 = 0; j2 < 4; j2++) {
                uint32_t addr = BHb
                    + (k0 + lrow8) * (B_STRIDE_H * 2)
                    + (nb + j2 * 16 + lk8) * 2;
                ldmatrix_x4_trans(bf[ks][j2][0], bf[ks][j2][1], bf[ks][j2][2], bf[ks][j2][3], addr);
            }
        }

        // refill fp32 stage p for kt+2 (this thread's chunks already converted)
        if (kt + 2 < KT) issue_stage(kt + 2, p);

        // MMA ks=0
#pragma unroll
        for (int i = 0; i < 4; i++)
#pragma unroll
            for (int j = 0; j < 8; j++) {
                const int j2 = j >> 1, h = (j & 1) * 2;
                mma_f16(acc[i][j][0], acc[i][j][1], acc[i][j][2], acc[i][j][3],
                        af[0][i][0], af[0][i][1], af[0][i][2], af[0][i][3],
                        bf[0][j2][h + 0], bf[0][j2][h + 1]);
            }

        // convert stage for kt+1 (hidden between the two MMA halves)
        if (kt + 1 < KT) {
            if (kt + 2 < KT) cp_wait<1>(); else cp_wait<0>();
            convert_stage(p ^ 1);
        }

        // MMA ks=1
#pragma unroll
        for (int i = 0; i < 4; i++)
#pragma unroll
            for (int j = 0; j < 8; j++) {
                const int j2 = j >> 1, h = (j & 1) * 2;
                mma_f16(acc[i][j][0], acc[i][j][1], acc[i][j][2], acc[i][j][3],
                        af[1][i][0], af[1][i][1], af[1][i][2], af[1][i][3],
                        bf[1][j2][h + 0], bf[1][j2][h + 1]);
            }

        __syncthreads();
    }

    // ---- epilogue (standard m16n8 C layout) ----
#pragma unroll
    for (int i = 0; i < 4; i++) {
        const int row0 = m_base + i * 16 + g;
#pragma unroll
        for (int j = 0; j < 8; j++) {
            const int col = nb + j * 8 + 2 * t;
            *(float2*)(Cb + (size_t)row0 * Nn + col) =
                make_float2(acc[i][j][0], acc[i][j][1]);
            *(float2*)(Cb + (size_t)(row0 + 8) * Nn + col) =
                make_float2(acc[i][j][2], acc[i][j][3]);
        }
    }
}

extern "C" void kernel_launch(void* const* d_in, const int* in_sizes, int n_in,
                              void* d_out, int out_size) {
    const float* x    = (const float*)d_in[0];  // [16, 256, 512]
    const float* path = (const float*)d_in[1];  // [16, 512, 2048]
    float* out = (float*)d_out;                 // [16, 256, 2048]

    cudaFuncSetAttribute(bmm_mma_f16_cp,
                         cudaFuncAttributeMaxDynamicSharedMemorySize, SMEM_BYTES);

    dim3 grid(Nn / BN, Mm / BM, 16);  // (16, 2, 16) = 512 CTAs
    bmm_mma_f16_cp<<<grid, THREADS, SMEM_BYTES>>>(x, path, out);
}